// round 3
// baseline (speedup 1.0000x reference)
#include <cuda_runtime.h>

// Problem constants
#define B_ 4096
#define S_ 200
#define E_ 128
#define H_ 64
#define G_ 32   // H/2

#define NT 512   // threads per CTA

// shared-memory pitches (floats)
#define KPITCH 129   // keys row pitch: odd -> conflict-free strided-s reads
#define H1PITCH 65
#define H2PITCH 33

// shared-memory float offsets
#define OFF_KEYS 0
#define OFF_H1   (S_ * KPITCH)                  // 25800
#define OFF_W1B  (OFF_H1 + S_ * H1PITCH)        // 38800
#define OFF_W2   (OFF_W1B + E_ * H_)            // 46992
#define OFF_H2   (OFF_W2 + H_ * G_)             // 49040
#define OFF_W3   (OFF_H2 + S_ * H2PITCH)        // 55640
#define OFF_QP   (OFF_W3 + G_)                  // 55672
#define OFF_SC   (OFF_QP + H_)                  // 55736
#define OFF_Q    (OFF_SC + S_)                  // 55936
#define OFF_RED  (OFF_Q + E_)                   // 56064 (32 slots)
#define OFF_PART (OFF_RED + 32)                 // 56096
#define SMEM_FLOATS (OFF_PART + 4 * E_)         // 56608
#define SMEM_BYTES (SMEM_FLOATS * 4)            // 226432 (< 227 KB sm_100a limit)

__global__ __launch_bounds__(NT, 1)
void attn_mlp_kernel(const float* __restrict__ query,
                     const float* __restrict__ keys,
                     const int*   __restrict__ mask,
                     const float* __restrict__ W1,
                     const float* __restrict__ b1,
                     const float* __restrict__ W2,
                     const float* __restrict__ b2,
                     const float* __restrict__ W3,
                     const float* __restrict__ b3,
                     float* __restrict__ out_att,
                     float* __restrict__ out_w)
{
    extern __shared__ float sm[];
    const int b = blockIdx.x;
    const int t = threadIdx.x;

    // ---------------- Phase 0: stage inputs into shared memory ----------------
    // keys[b] : 200x128 f32, stored with pitch 129
    {
        const float4* kg = reinterpret_cast<const float4*>(keys + (size_t)b * S_ * E_);
        for (int fi = t; fi < (S_ * E_) / 4; fi += NT) {
            float4 v = kg[fi];
            int s = fi >> 5;            // 32 float4 per 128-wide row
            int c = (fi & 31) * 4;
            float* dst = &sm[OFF_KEYS + s * KPITCH + c];
            dst[0] = v.x; dst[1] = v.y; dst[2] = v.z; dst[3] = v.w;
        }
    }
    // W1 bottom half (keys part), rows 128..255 -> [e][j], pitch 64
    {
        const float4* wg = reinterpret_cast<const float4*>(W1 + E_ * H_);
        for (int fi = t; fi < (E_ * H_) / 4; fi += NT) {
            float4 v = wg[fi];
            float* dst = &sm[OFF_W1B + fi * 4];
            dst[0] = v.x; dst[1] = v.y; dst[2] = v.z; dst[3] = v.w;
        }
    }
    // W2 : 64x32
    {
        const float4* wg = reinterpret_cast<const float4*>(W2);
        for (int fi = t; fi < (H_ * G_) / 4; fi += NT) {
            float4 v = wg[fi];
            float* dst = &sm[OFF_W2 + fi * 4];
            dst[0] = v.x; dst[1] = v.y; dst[2] = v.z; dst[3] = v.w;
        }
    }
    if (t < G_) sm[OFF_W3 + t] = W3[t];
    if (t < E_) sm[OFF_Q + t] = query[(size_t)b * E_ + t];
    __syncthreads();

    // ---------------- Phase 1: query part of layer 1 (once per b) ----------------
    // qp[j] = b1[j] + sum_e q[e] * W1[e][j]   (W1 top half via L2, coalesced)
    if (t < H_) {
        float acc = b1[t];
        #pragma unroll 8
        for (int e = 0; e < E_; e++)
            acc += sm[OFF_Q + e] * W1[e * H_ + t];
        sm[OFF_QP + t] = acc;
    }
    __syncthreads();

    // ---------------- Phase 2: layer 1  h1[s][j] = relu(qp[j] + K[s,:]·W1b[:,j]) ----------------
    {
        const int jt = t & 15;     // j tile = 4*jt .. 4*jt+3
        const int st = t >> 4;     // s rows: st + 32*i, i = 0..6
        float acc[7][4];
        #pragma unroll
        for (int i = 0; i < 7; i++) {
            acc[i][0] = 0.f; acc[i][1] = 0.f; acc[i][2] = 0.f; acc[i][3] = 0.f;
        }
        int kbase[7];
        #pragma unroll
        for (int i = 0; i < 7; i++) kbase[i] = OFF_KEYS + (st + 32 * i) * KPITCH;

        const float4* w1v = reinterpret_cast<const float4*>(&sm[OFF_W1B]);
        #pragma unroll 4
        for (int e = 0; e < E_; e++) {
            float4 w = w1v[e * 16 + jt];
            #pragma unroll
            for (int i = 0; i < 7; i++) {
                float kv = sm[kbase[i] + e];   // 2-way broadcast per warp, conflict-free (pitch 129)
                acc[i][0] += kv * w.x;
                acc[i][1] += kv * w.y;
                acc[i][2] += kv * w.z;
                acc[i][3] += kv * w.w;
            }
        }
        float qp0 = sm[OFF_QP + 4 * jt + 0];
        float qp1 = sm[OFF_QP + 4 * jt + 1];
        float qp2 = sm[OFF_QP + 4 * jt + 2];
        float qp3 = sm[OFF_QP + 4 * jt + 3];
        #pragma unroll
        for (int i = 0; i < 7; i++) {
            int s = st + 32 * i;
            if (s < S_) {
                float* d = &sm[OFF_H1 + s * H1PITCH + 4 * jt];
                d[0] = fmaxf(acc[i][0] + qp0, 0.f);
                d[1] = fmaxf(acc[i][1] + qp1, 0.f);
                d[2] = fmaxf(acc[i][2] + qp2, 0.f);
                d[3] = fmaxf(acc[i][3] + qp3, 0.f);
            }
        }
    }
    __syncthreads();

    // ---------------- Phase 3: layer 2  h2[s][g] = relu(h1[s,:]·W2[:,g] + b2[g]) ----------------
    {
        const int jt = t & 7;      // g tile = 4*jt .. 4*jt+3
        const int st = t >> 3;     // s rows: st + 64*i, i = 0..3
        float acc[4][4];
        #pragma unroll
        for (int i = 0; i < 4; i++) {
            acc[i][0] = 0.f; acc[i][1] = 0.f; acc[i][2] = 0.f; acc[i][3] = 0.f;
        }
        const float4* w2v = reinterpret_cast<const float4*>(&sm[OFF_W2]);
        #pragma unroll 4
        for (int e = 0; e < H_; e++) {
            float4 w = w2v[e * 8 + jt];
            #pragma unroll
            for (int i = 0; i < 4; i++) {
                // rows st+64i; for s >= 200 this reads in-bounds junk, guarded at store
                float hv = sm[OFF_H1 + (st + 64 * i) * H1PITCH + e];
                acc[i][0] += hv * w.x;
                acc[i][1] += hv * w.y;
                acc[i][2] += hv * w.z;
                acc[i][3] += hv * w.w;
            }
        }
        float bb0 = b2[4 * jt + 0];
        float bb1 = b2[4 * jt + 1];
        float bb2 = b2[4 * jt + 2];
        float bb3 = b2[4 * jt + 3];
        #pragma unroll
        for (int i = 0; i < 4; i++) {
            int s = st + 64 * i;
            if (s < S_) {
                float* d = &sm[OFF_H2 + s * H2PITCH + 4 * jt];
                d[0] = fmaxf(acc[i][0] + bb0, 0.f);
                d[1] = fmaxf(acc[i][1] + bb1, 0.f);
                d[2] = fmaxf(acc[i][2] + bb2, 0.f);
                d[3] = fmaxf(acc[i][3] + bb3, 0.f);
            }
        }
    }
    __syncthreads();

    // ---------------- Phase 4: layer 3 + mask -> scores ----------------
    if (t < S_) {
        float acc = b3[0];
        #pragma unroll
        for (int g = 0; g < G_; g++)
            acc += sm[OFF_H2 + t * H2PITCH + g] * sm[OFF_W3 + g];
        if (mask[(size_t)b * S_ + t] == 0) acc = -1e9f;
        sm[OFF_SC + t] = acc;
    }
    __syncthreads();

    // ---------------- Phase 5: softmax over s ----------------
    const int lane = t & 31;
    const int warp = t >> 5;
    {
        float v = (t < S_) ? sm[OFF_SC + t] : -3.4e38f;
        #pragma unroll
        for (int o = 16; o > 0; o >>= 1)
            v = fmaxf(v, __shfl_xor_sync(0xFFFFFFFFu, v, o));
        if (lane == 0) sm[OFF_RED + warp] = v;
    }
    __syncthreads();
    float mx = sm[OFF_RED + 0];
    #pragma unroll
    for (int w = 1; w < NT / 32; w++) mx = fmaxf(mx, sm[OFF_RED + w]);

    float ev = (t < S_) ? expf(sm[OFF_SC + t] - mx) : 0.f;
    {
        float v = ev;
        #pragma unroll
        for (int o = 16; o > 0; o >>= 1)
            v += __shfl_xor_sync(0xFFFFFFFFu, v, o);
        if (lane == 0) sm[OFF_RED + 16 + warp] = v;
    }
    __syncthreads();
    float tot = sm[OFF_RED + 16];
    #pragma unroll
    for (int w = 1; w < NT / 32; w++) tot += sm[OFF_RED + 16 + w];
    float inv = 1.0f / tot;
    if (t < S_) {
        float w = ev * inv;
        sm[OFF_SC + t] = w;                         // reuse scores slot as weights
        out_w[(size_t)b * S_ + t] = w;
    }
    __syncthreads();

    // ---------------- Phase 6: attended = sum_s w[s] * keys[s,:] ----------------
    {
        const int e = t & 127;
        const int q = t >> 7;          // quarter: s in [q*50, q*50+50)
        float acc = 0.f;
        const int s0 = q * 50;
        #pragma unroll 5
        for (int s = s0; s < s0 + 50; s++)
            acc += sm[OFF_SC + s] * sm[OFF_KEYS + s * KPITCH + e];
        sm[OFF_PART + q * E_ + e] = acc;
    }
    __syncthreads();
    if (t < E_)
        out_att[(size_t)b * E_ + t] = sm[OFF_PART + t] + sm[OFF_PART + E_ + t]
                                    + sm[OFF_PART + 2 * E_ + t] + sm[OFF_PART + 3 * E_ + t];
}

extern "C" void kernel_launch(void* const* d_in, const int* in_sizes, int n_in,
                              void* d_out, int out_size) {
    const float* query = (const float*)d_in[0];
    const float* keys  = (const float*)d_in[1];
    const int*   mask  = (const int*)  d_in[2];
    const float* W1    = (const float*)d_in[3];
    const float* b1    = (const float*)d_in[4];
    const float* W2    = (const float*)d_in[5];
    const float* b2    = (const float*)d_in[6];
    const float* W3    = (const float*)d_in[7];
    const float* b3    = (const float*)d_in[8];

    float* out = (float*)d_out;
    float* out_att = out;                       // [B, E] first (tuple order)
    float* out_w   = out + (size_t)B_ * E_;     // [B, S] second

    cudaFuncSetAttribute(attn_mlp_kernel,
                         cudaFuncAttributeMaxDynamicSharedMemorySize, SMEM_BYTES);

    attn_mlp_kernel<<<B_, NT, SMEM_BYTES>>>(query, keys, mask,
                                            W1, b1, W2, b2, W3, b3,
                                            out_att, out_w);
}

// round 5
// speedup vs baseline: 1.1206x; 1.1206x over previous
#include <cuda_runtime.h>

// Problem constants
#define B_ 4096
#define S_ 200
#define E_ 128
#define H_ 64
#define G_ 32   // H/2

#define NT 512   // threads per CTA

// shared-memory pitches (floats). 16B-aligned (float4 loads) and ≡4 mod 32
// (conflict-free for the strided-s access patterns used below).
#define KPITCH 132
#define H1PITCH 68
#define H2PITCH 33

// shared-memory float offsets (all float4-aligned where vector-accessed)
#define OFF_KEYS 0
#define OFF_H1   (S_ * KPITCH)                  // 26400
#define OFF_W1B  (OFF_H1 + S_ * H1PITCH)        // 40000
#define OFF_W2   (OFF_W1B + E_ * H_)            // 48192
#define OFF_H2   (OFF_W2 + H_ * G_)             // 50240
#define OFF_W3   (OFF_H2 + S_ * H2PITCH)        // 56840
#define OFF_QP   (OFF_W3 + G_)                  // 56872
#define OFF_SC   (OFF_QP + H_)                  // 56936
#define OFF_Q    (OFF_SC + S_)                  // 57136
#define OFF_RED  (OFF_Q + E_)                   // 57264 (32 slots)
#define OFF_PART (OFF_RED + 32)                 // 57296
#define SMEM_FLOATS (OFF_PART + 4 * E_)         // 57808
#define SMEM_BYTES (SMEM_FLOATS * 4)            // 231232 (< 232448 sm_100a limit)

// ---- packed f32x2 helpers (Blackwell FFMA2 path, PTX-only) ----
__device__ __forceinline__ unsigned long long pack2(float lo, float hi) {
    unsigned long long r;
    asm("mov.b64 %0, {%1, %2};" : "=l"(r) : "f"(lo), "f"(hi));
    return r;
}
__device__ __forceinline__ void fma2(unsigned long long& d,
                                     unsigned long long a,
                                     unsigned long long b) {
    asm("fma.rn.f32x2 %0, %1, %2, %0;" : "+l"(d) : "l"(a), "l"(b));
}
__device__ __forceinline__ float2 unpack2(unsigned long long v) {
    float2 f;
    asm("mov.b64 {%0, %1}, %2;" : "=f"(f.x), "=f"(f.y) : "l"(v));
    return f;
}

__global__ __launch_bounds__(NT, 1)
void attn_mlp_kernel(const float* __restrict__ query,
                     const float* __restrict__ keys,
                     const int*   __restrict__ mask,
                     const float* __restrict__ W1,
                     const float* __restrict__ b1,
                     const float* __restrict__ W2,
                     const float* __restrict__ b2,
                     const float* __restrict__ W3,
                     const float* __restrict__ b3,
                     float* __restrict__ out_att,
                     float* __restrict__ out_w)
{
    extern __shared__ float sm[];
    const int b = blockIdx.x;
    const int t = threadIdx.x;

    // ---------------- Phase 0: stage inputs into shared memory ----------------
    {
        const float4* kg = reinterpret_cast<const float4*>(keys + (size_t)b * S_ * E_);
        for (int fi = t; fi < (S_ * E_) / 4; fi += NT) {
            float4 v = kg[fi];
            int s = fi >> 5;            // 32 float4 per 128-wide row
            int c = (fi & 31) * 4;
            *reinterpret_cast<float4*>(&sm[OFF_KEYS + s * KPITCH + c]) = v;
        }
    }
    // W1 bottom half (keys part), rows 128..255 -> [e][j], pitch 64
    {
        const float4* wg = reinterpret_cast<const float4*>(W1 + E_ * H_);
        for (int fi = t; fi < (E_ * H_) / 4; fi += NT)
            *reinterpret_cast<float4*>(&sm[OFF_W1B + fi * 4]) = wg[fi];
    }
    // W2 : 64x32 -> [e][g]
    {
        const float4* wg = reinterpret_cast<const float4*>(W2);
        for (int fi = t; fi < (H_ * G_) / 4; fi += NT)
            *reinterpret_cast<float4*>(&sm[OFF_W2 + fi * 4]) = wg[fi];
    }
    if (t < G_) sm[OFF_W3 + t] = W3[t];
    if (t < E_) sm[OFF_Q + t] = query[(size_t)b * E_ + t];
    __syncthreads();

    // ---------------- Phase 1: query part of layer 1 (once per b) ----------------
    if (t < H_) {
        float acc = b1[t];
        #pragma unroll 8
        for (int e = 0; e < E_; e++)
            acc += sm[OFF_Q + e] * W1[e * H_ + t];
        sm[OFF_QP + t] = acc;
    }
    __syncthreads();

    // ------- Phase 2: layer 1  h1[s][j] = relu(qp[j] + K[s,:]·W1b[:,j]) -------
    // f32x2 packed FMA, j-pairs; e-blocked by 4 with float4 kv loads.
    {
        const int jt = t & 15;     // j tile = 4*jt .. 4*jt+3  (pairs: lo=j0j1, hi=j2j3)
        const int st = t >> 4;     // s rows: st + 32*i, i = 0..6
        unsigned long long acc0[7], acc1[7];
        #pragma unroll
        for (int i = 0; i < 7; i++) { acc0[i] = 0ull; acc1[i] = 0ull; }

        int kbase[7];
        #pragma unroll
        for (int i = 0; i < 7; i++) kbase[i] = OFF_KEYS + (st + 32 * i) * KPITCH;

        const ulonglong2* w1v = reinterpret_cast<const ulonglong2*>(&sm[OFF_W1B]);
        #pragma unroll 1
        for (int eb = 0; eb < E_ / 4; eb++) {
            ulonglong2 w0 = w1v[(4 * eb + 0) * 16 + jt];
            ulonglong2 w1 = w1v[(4 * eb + 1) * 16 + jt];
            ulonglong2 w2 = w1v[(4 * eb + 2) * 16 + jt];
            ulonglong2 w3 = w1v[(4 * eb + 3) * 16 + jt];
            #pragma unroll
            for (int i = 0; i < 7; i++) {
                float4 kv = *reinterpret_cast<const float4*>(&sm[kbase[i] + 4 * eb]);
                unsigned long long p0 = pack2(kv.x, kv.x);
                unsigned long long p1 = pack2(kv.y, kv.y);
                unsigned long long p2 = pack2(kv.z, kv.z);
                unsigned long long p3 = pack2(kv.w, kv.w);
                fma2(acc0[i], p0, w0.x); fma2(acc1[i], p0, w0.y);
                fma2(acc0[i], p1, w1.x); fma2(acc1[i], p1, w1.y);
                fma2(acc0[i], p2, w2.x); fma2(acc1[i], p2, w2.y);
                fma2(acc0[i], p3, w3.x); fma2(acc1[i], p3, w3.y);
            }
        }
        float qp0 = sm[OFF_QP + 4 * jt + 0];
        float qp1 = sm[OFF_QP + 4 * jt + 1];
        float qp2 = sm[OFF_QP + 4 * jt + 2];
        float qp3 = sm[OFF_QP + 4 * jt + 3];
        #pragma unroll
        for (int i = 0; i < 7; i++) {
            int s = st + 32 * i;
            if (s < S_) {
                float2 a = unpack2(acc0[i]);
                float2 c = unpack2(acc1[i]);
                float4 r;
                r.x = fmaxf(a.x + qp0, 0.f);
                r.y = fmaxf(a.y + qp1, 0.f);
                r.z = fmaxf(c.x + qp2, 0.f);
                r.w = fmaxf(c.y + qp3, 0.f);
                *reinterpret_cast<float4*>(&sm[OFF_H1 + s * H1PITCH + 4 * jt]) = r;
            }
        }
    }
    __syncthreads();

    // ------- Phase 3: layer 2  h2[s][g] = relu(h1[s,:]·W2[:,g] + b2[g]) -------
    {
        const int jt = t & 7;      // g tile = 4*jt .. 4*jt+3
        const int st = t >> 3;     // s rows: st + 64*i, i = 0..3
        unsigned long long acc0[4], acc1[4];
        #pragma unroll
        for (int i = 0; i < 4; i++) { acc0[i] = 0ull; acc1[i] = 0ull; }

        int hbase[4];
        #pragma unroll
        for (int i = 0; i < 4; i++) hbase[i] = OFF_H1 + (st + 64 * i) * H1PITCH;

        const ulonglong2* w2v = reinterpret_cast<const ulonglong2*>(&sm[OFF_W2]);
        #pragma unroll 2
        for (int eb = 0; eb < H_ / 4; eb++) {
            ulonglong2 w0 = w2v[(4 * eb + 0) * 8 + jt];
            ulonglong2 w1 = w2v[(4 * eb + 1) * 8 + jt];
            ulonglong2 w2_ = w2v[(4 * eb + 2) * 8 + jt];
            ulonglong2 w3 = w2v[(4 * eb + 3) * 8 + jt];
            #pragma unroll
            for (int i = 0; i < 4; i++) {
                // rows s >= 200 read in-bounds junk, guarded at store
                float4 hv = *reinterpret_cast<const float4*>(&sm[hbase[i] + 4 * eb]);
                unsigned long long p0 = pack2(hv.x, hv.x);
                unsigned long long p1 = pack2(hv.y, hv.y);
                unsigned long long p2 = pack2(hv.z, hv.z);
                unsigned long long p3 = pack2(hv.w, hv.w);
                fma2(acc0[i], p0, w0.x);  fma2(acc1[i], p0, w0.y);
                fma2(acc0[i], p1, w1.x);  fma2(acc1[i], p1, w1.y);
                fma2(acc0[i], p2, w2_.x); fma2(acc1[i], p2, w2_.y);
                fma2(acc0[i], p3, w3.x);  fma2(acc1[i], p3, w3.y);
            }
        }
        float bb0 = b2[4 * jt + 0];
        float bb1 = b2[4 * jt + 1];
        float bb2 = b2[4 * jt + 2];
        float bb3 = b2[4 * jt + 3];
        #pragma unroll
        for (int i = 0; i < 4; i++) {
            int s = st + 64 * i;
            if (s < S_) {
                float2 a = unpack2(acc0[i]);
                float2 c = unpack2(acc1[i]);
                float* d = &sm[OFF_H2 + s * H2PITCH + 4 * jt];
                d[0] = fmaxf(a.x + bb0, 0.f);
                d[1] = fmaxf(a.y + bb1, 0.f);
                d[2] = fmaxf(c.x + bb2, 0.f);
                d[3] = fmaxf(c.y + bb3, 0.f);
            }
        }
    }
    __syncthreads();

    // ---------------- Phase 4: layer 3 + mask -> scores ----------------
    if (t < S_) {
        float acc = b3[0];
        #pragma unroll
        for (int g = 0; g < G_; g++)
            acc += sm[OFF_H2 + t * H2PITCH + g] * sm[OFF_W3 + g];
        if (mask[(size_t)b * S_ + t] == 0) acc = -1e9f;
        sm[OFF_SC + t] = acc;
    }
    __syncthreads();

    // ---------------- Phase 5: softmax over s ----------------
    const int lane = t & 31;
    const int warp = t >> 5;
    {
        float v = (t < S_) ? sm[OFF_SC + t] : -3.4e38f;
        #pragma unroll
        for (int o = 16; o > 0; o >>= 1)
            v = fmaxf(v, __shfl_xor_sync(0xFFFFFFFFu, v, o));
        if (lane == 0) sm[OFF_RED + warp] = v;
    }
    __syncthreads();
    float mx = sm[OFF_RED + 0];
    #pragma unroll
    for (int w = 1; w < NT / 32; w++) mx = fmaxf(mx, sm[OFF_RED + w]);

    float ev = (t < S_) ? expf(sm[OFF_SC + t] - mx) : 0.f;
    {
        float v = ev;
        #pragma unroll
        for (int o = 16; o > 0; o >>= 1)
            v += __shfl_xor_sync(0xFFFFFFFFu, v, o);
        if (lane == 0) sm[OFF_RED + 16 + warp] = v;
    }
    __syncthreads();
    float tot = sm[OFF_RED + 16];
    #pragma unroll
    for (int w = 1; w < NT / 32; w++) tot += sm[OFF_RED + 16 + w];
    float inv = 1.0f / tot;
    if (t < S_) {
        float w = ev * inv;
        sm[OFF_SC + t] = w;                         // reuse scores slot as weights
        out_w[(size_t)b * S_ + t] = w;
    }
    __syncthreads();

    // ---------------- Phase 6: attended = sum_s w[s] * keys[s,:] ----------------
    {
        const int e = t & 127;
        const int q = t >> 7;          // quarter: s in [q*50, q*50+50)
        float acc = 0.f;
        const int s0 = q * 50;
        #pragma unroll 5
        for (int s = s0; s < s0 + 50; s++)
            acc += sm[OFF_SC + s] * sm[OFF_KEYS + s * KPITCH + e];
        sm[OFF_PART + q * E_ + e] = acc;
    }
    __syncthreads();
    if (t < E_)
        out_att[(size_t)b * E_ + t] = sm[OFF_PART + t] + sm[OFF_PART + E_ + t]
                                    + sm[OFF_PART + 2 * E_ + t] + sm[OFF_PART + 3 * E_ + t];
}

extern "C" void kernel_launch(void* const* d_in, const int* in_sizes, int n_in,
                              void* d_out, int out_size) {
    const float* query = (const float*)d_in[0];
    const float* keys  = (const float*)d_in[1];
    const int*   mask  = (const int*)  d_in[2];
    const float* W1    = (const float*)d_in[3];
    const float* b1    = (const float*)d_in[4];
    const float* W2    = (const float*)d_in[5];
    const float* b2    = (const float*)d_in[6];
    const float* W3    = (const float*)d_in[7];
    const float* b3    = (const float*)d_in[8];

    float* out = (float*)d_out;
    float* out_att = out;                       // [B, E] first (tuple order)
    float* out_w   = out + (size_t)B_ * E_;     // [B, S] second

    cudaFuncSetAttribute(attn_mlp_kernel,
                         cudaFuncAttributeMaxDynamicSharedMemorySize, SMEM_BYTES);

    attn_mlp_kernel<<<B_, NT, SMEM_BYTES>>>(query, keys, mask,
                                            W1, b1, W2, b2, W3, b3,
                                            out_att, out_w);
}

// round 6
// speedup vs baseline: 1.1229x; 1.0021x over previous
#include <cuda_runtime.h>

// Problem constants
#define B_ 4096
#define S_ 200
#define E_ 128
#define H_ 64
#define G_ 32   // H/2

#define NT 512   // threads per CTA

// shared-memory pitches (floats). 16B-aligned (float4 loads) and ≡4 mod 32
// (conflict-free for the strided-s access patterns used below).
#define KPITCH 132
#define H1PITCH 68
#define H2PITCH 33

// shared-memory float offsets (all float4-aligned where vector-accessed)
#define OFF_KEYS 0
#define OFF_H1   (S_ * KPITCH)                  // 26400
#define OFF_W1B  (OFF_H1 + S_ * H1PITCH)        // 40000
#define OFF_W2   (OFF_W1B + E_ * H_)            // 48192
#define OFF_H2   (OFF_W2 + H_ * G_)             // 50240
#define OFF_W3   (OFF_H2 + S_ * H2PITCH)        // 56840
#define OFF_QP   (OFF_W3 + G_)                  // 56872
#define OFF_SC   (OFF_QP + H_)                  // 56936
#define OFF_Q    (OFF_SC + S_)                  // 57136
#define OFF_RED  (OFF_Q + E_)                   // 57264 (32 slots)
#define OFF_PART (OFF_RED + 32)                 // 57296
#define SMEM_FLOATS (OFF_PART + 4 * E_)         // 57808
#define SMEM_BYTES (SMEM_FLOATS * 4)            // 231232 (< 232448 sm_100a limit)

// ---- packed f32x2 helpers (Blackwell FFMA2 path, PTX-only) ----
__device__ __forceinline__ unsigned long long pack2(float lo, float hi) {
    unsigned long long r;
    asm("mov.b64 %0, {%1, %2};" : "=l"(r) : "f"(lo), "f"(hi));
    return r;
}
__device__ __forceinline__ void fma2(unsigned long long& d,
                                     unsigned long long a,
                                     unsigned long long b) {
    asm("fma.rn.f32x2 %0, %1, %2, %0;" : "+l"(d) : "l"(a), "l"(b));
}
__device__ __forceinline__ float2 unpack2(unsigned long long v) {
    float2 f;
    asm("mov.b64 {%0, %1}, %2;" : "=f"(f.x), "=f"(f.y) : "l"(v));
    return f;
}

__global__ __launch_bounds__(NT, 1)
void attn_mlp_kernel(const float* __restrict__ query,
                     const float* __restrict__ keys,
                     const int*   __restrict__ mask,
                     const float* __restrict__ W1,
                     const float* __restrict__ b1,
                     const float* __restrict__ W2,
                     const float* __restrict__ b2,
                     const float* __restrict__ W3,
                     const float* __restrict__ b3,
                     float* __restrict__ out_att,
                     float* __restrict__ out_w)
{
    extern __shared__ float sm[];
    const int b = blockIdx.x;
    const int t = threadIdx.x;

    // ---------------- Phase 0: stage inputs into shared memory ----------------
    {
        const float4* kg = reinterpret_cast<const float4*>(keys + (size_t)b * S_ * E_);
        for (int fi = t; fi < (S_ * E_) / 4; fi += NT) {
            float4 v = kg[fi];
            int s = fi >> 5;            // 32 float4 per 128-wide row
            int c = (fi & 31) * 4;
            *reinterpret_cast<float4*>(&sm[OFF_KEYS + s * KPITCH + c]) = v;
        }
    }
    // W1 bottom half (keys part), rows 128..255 -> [e][j], pitch 64
    {
        const float4* wg = reinterpret_cast<const float4*>(W1 + E_ * H_);
        for (int fi = t; fi < (E_ * H_) / 4; fi += NT)
            *reinterpret_cast<float4*>(&sm[OFF_W1B + fi * 4]) = wg[fi];
    }
    // W2 : 64x32 -> [e][g]
    {
        const float4* wg = reinterpret_cast<const float4*>(W2);
        for (int fi = t; fi < (H_ * G_) / 4; fi += NT)
            *reinterpret_cast<float4*>(&sm[OFF_W2 + fi * 4]) = wg[fi];
    }
    if (t < G_) sm[OFF_W3 + t] = W3[t];
    if (t < E_) sm[OFF_Q + t] = query[(size_t)b * E_ + t];
    __syncthreads();

    // ---------------- Phase 1: query part of layer 1 (once per b) ----------------
    if (t < H_) {
        float acc = b1[t];
        #pragma unroll 8
        for (int e = 0; e < E_; e++)
            acc += sm[OFF_Q + e] * W1[e * H_ + t];
        sm[OFF_QP + t] = acc;
    }
    __syncthreads();

    // ------- Phase 2: layer 1  h1[s][j] = relu(qp[j] + K[s,:]·W1b[:,j]) -------
    // f32x2 packed FMA, j-pairs; e-blocked by 4 with float4 kv loads.
    {
        const int jt = t & 15;     // j tile = 4*jt .. 4*jt+3  (pairs: lo=j0j1, hi=j2j3)
        const int st = t >> 4;     // s rows: st + 32*i, i = 0..6
        unsigned long long acc0[7], acc1[7];
        #pragma unroll
        for (int i = 0; i < 7; i++) { acc0[i] = 0ull; acc1[i] = 0ull; }

        int kbase[7];
        #pragma unroll
        for (int i = 0; i < 7; i++) kbase[i] = OFF_KEYS + (st + 32 * i) * KPITCH;

        const ulonglong2* w1v = reinterpret_cast<const ulonglong2*>(&sm[OFF_W1B]);
        #pragma unroll 1
        for (int eb = 0; eb < E_ / 4; eb++) {
            ulonglong2 w0 = w1v[(4 * eb + 0) * 16 + jt];
            ulonglong2 w1 = w1v[(4 * eb + 1) * 16 + jt];
            ulonglong2 w2 = w1v[(4 * eb + 2) * 16 + jt];
            ulonglong2 w3 = w1v[(4 * eb + 3) * 16 + jt];
            #pragma unroll
            for (int i = 0; i < 7; i++) {
                float4 kv = *reinterpret_cast<const float4*>(&sm[kbase[i] + 4 * eb]);
                unsigned long long p0 = pack2(kv.x, kv.x);
                unsigned long long p1 = pack2(kv.y, kv.y);
                unsigned long long p2 = pack2(kv.z, kv.z);
                unsigned long long p3 = pack2(kv.w, kv.w);
                fma2(acc0[i], p0, w0.x); fma2(acc1[i], p0, w0.y);
                fma2(acc0[i], p1, w1.x); fma2(acc1[i], p1, w1.y);
                fma2(acc0[i], p2, w2.x); fma2(acc1[i], p2, w2.y);
                fma2(acc0[i], p3, w3.x); fma2(acc1[i], p3, w3.y);
            }
        }
        float qp0 = sm[OFF_QP + 4 * jt + 0];
        float qp1 = sm[OFF_QP + 4 * jt + 1];
        float qp2 = sm[OFF_QP + 4 * jt + 2];
        float qp3 = sm[OFF_QP + 4 * jt + 3];
        #pragma unroll
        for (int i = 0; i < 7; i++) {
            int s = st + 32 * i;
            if (s < S_) {
                float2 a = unpack2(acc0[i]);
                float2 c = unpack2(acc1[i]);
                float4 r;
                r.x = fmaxf(a.x + qp0, 0.f);
                r.y = fmaxf(a.y + qp1, 0.f);
                r.z = fmaxf(c.x + qp2, 0.f);
                r.w = fmaxf(c.y + qp3, 0.f);
                *reinterpret_cast<float4*>(&sm[OFF_H1 + s * H1PITCH + 4 * jt]) = r;
            }
        }
    }
    __syncthreads();

    // ------- Phase 3: layer 2  h2[s][g] = relu(h1[s,:]·W2[:,g] + b2[g]) -------
    {
        const int jt = t & 7;      // g tile = 4*jt .. 4*jt+3
        const int st = t >> 3;     // s rows: st + 64*i, i = 0..3
        unsigned long long acc0[4], acc1[4];
        #pragma unroll
        for (int i = 0; i < 4; i++) { acc0[i] = 0ull; acc1[i] = 0ull; }

        int hbase[4];
        #pragma unroll
        for (int i = 0; i < 4; i++) hbase[i] = OFF_H1 + (st + 64 * i) * H1PITCH;

        const ulonglong2* w2v = reinterpret_cast<const ulonglong2*>(&sm[OFF_W2]);
        #pragma unroll 2
        for (int eb = 0; eb < H_ / 4; eb++) {
            ulonglong2 w0 = w2v[(4 * eb + 0) * 8 + jt];
            ulonglong2 w1 = w2v[(4 * eb + 1) * 8 + jt];
            ulonglong2 w2_ = w2v[(4 * eb + 2) * 8 + jt];
            ulonglong2 w3 = w2v[(4 * eb + 3) * 8 + jt];
            #pragma unroll
            for (int i = 0; i < 4; i++) {
                // rows s >= 200 read in-bounds junk, guarded at store
                float4 hv = *reinterpret_cast<const float4*>(&sm[hbase[i] + 4 * eb]);
                unsigned long long p0 = pack2(hv.x, hv.x);
                unsigned long long p1 = pack2(hv.y, hv.y);
                unsigned long long p2 = pack2(hv.z, hv.z);
                unsigned long long p3 = pack2(hv.w, hv.w);
                fma2(acc0[i], p0, w0.x);  fma2(acc1[i], p0, w0.y);
                fma2(acc0[i], p1, w1.x);  fma2(acc1[i], p1, w1.y);
                fma2(acc0[i], p2, w2_.x); fma2(acc1[i], p2, w2_.y);
                fma2(acc0[i], p3, w3.x);  fma2(acc1[i], p3, w3.y);
            }
        }
        float bb0 = b2[4 * jt + 0];
        float bb1 = b2[4 * jt + 1];
        float bb2 = b2[4 * jt + 2];
        float bb3 = b2[4 * jt + 3];
        #pragma unroll
        for (int i = 0; i < 4; i++) {
            int s = st + 64 * i;
            if (s < S_) {
                float2 a = unpack2(acc0[i]);
                float2 c = unpack2(acc1[i]);
                float* d = &sm[OFF_H2 + s * H2PITCH + 4 * jt];
                d[0] = fmaxf(a.x + bb0, 0.f);
                d[1] = fmaxf(a.y + bb1, 0.f);
                d[2] = fmaxf(c.x + bb2, 0.f);
                d[3] = fmaxf(c.y + bb3, 0.f);
            }
        }
    }
    __syncthreads();

    // ---------------- Phase 4: layer 3 + mask -> scores ----------------
    if (t < S_) {
        float acc = b3[0];
        #pragma unroll
        for (int g = 0; g < G_; g++)
            acc += sm[OFF_H2 + t * H2PITCH + g] * sm[OFF_W3 + g];
        if (mask[(size_t)b * S_ + t] == 0) acc = -1e9f;
        sm[OFF_SC + t] = acc;
    }
    __syncthreads();

    // ---------------- Phase 5: softmax over s ----------------
    const int lane = t & 31;
    const int warp = t >> 5;
    {
        float v = (t < S_) ? sm[OFF_SC + t] : -3.4e38f;
        #pragma unroll
        for (int o = 16; o > 0; o >>= 1)
            v = fmaxf(v, __shfl_xor_sync(0xFFFFFFFFu, v, o));
        if (lane == 0) sm[OFF_RED + warp] = v;
    }
    __syncthreads();
    float mx = sm[OFF_RED + 0];
    #pragma unroll
    for (int w = 1; w < NT / 32; w++) mx = fmaxf(mx, sm[OFF_RED + w]);

    float ev = (t < S_) ? expf(sm[OFF_SC + t] - mx) : 0.f;
    {
        float v = ev;
        #pragma unroll
        for (int o = 16; o > 0; o >>= 1)
            v += __shfl_xor_sync(0xFFFFFFFFu, v, o);
        if (lane == 0) sm[OFF_RED + 16 + warp] = v;
    }
    __syncthreads();
    float tot = sm[OFF_RED + 16];
    #pragma unroll
    for (int w = 1; w < NT / 32; w++) tot += sm[OFF_RED + 16 + w];
    float inv = 1.0f / tot;
    if (t < S_) {
        float w = ev * inv;
        sm[OFF_SC + t] = w;                         // reuse scores slot as weights
        out_w[(size_t)b * S_ + t] = w;
    }
    __syncthreads();

    // ---------------- Phase 6: attended = sum_s w[s] * keys[s,:] ----------------
    {
        const int e = t & 127;
        const int q = t >> 7;          // quarter: s in [q*50, q*50+50)
        float acc = 0.f;
        const int s0 = q * 50;
        #pragma unroll 5
        for (int s = s0; s < s0 + 50; s++)
            acc += sm[OFF_SC + s] * sm[OFF_KEYS + s * KPITCH + e];
        sm[OFF_PART + q * E_ + e] = acc;
    }
    __syncthreads();
    if (t < E_)
        out_att[(size_t)b * E_ + t] = sm[OFF_PART + t] + sm[OFF_PART + E_ + t]
                                    + sm[OFF_PART + 2 * E_ + t] + sm[OFF_PART + 3 * E_ + t];
}

extern "C" void kernel_launch(void* const* d_in, const int* in_sizes, int n_in,
                              void* d_out, int out_size) {
    const float* query = (const float*)d_in[0];
    const float* keys  = (const float*)d_in[1];
    const int*   mask  = (const int*)  d_in[2];
    const float* W1    = (const float*)d_in[3];
    const float* b1    = (const float*)d_in[4];
    const float* W2    = (const float*)d_in[5];
    const float* b2    = (const float*)d_in[6];
    const float* W3    = (const float*)d_in[7];
    const float* b3    = (const float*)d_in[8];

    float* out = (float*)d_out;
    float* out_att = out;                       // [B, E] first (tuple order)
    float* out_w   = out + (size_t)B_ * E_;     // [B, S] second

    cudaFuncSetAttribute(attn_mlp_kernel,
                         cudaFuncAttributeMaxDynamicSharedMemorySize, SMEM_BYTES);

    attn_mlp_kernel<<<B_, NT, SMEM_BYTES>>>(query, keys, mask,
                                            W1, b1, W2, b2, W3, b3,
                                            out_att, out_w);
}

// round 8
// speedup vs baseline: 1.1839x; 1.0543x over previous
#include <cuda_runtime.h>

// Problem constants
#define B_ 4096
#define S_ 200
#define E_ 128
#define H_ 64
#define G_ 32   // H/2

#define NT 512   // threads per CTA

// pitches (floats): multiples of 4 (16B alignment), ≡4 mod 32 where strided
#define KPITCH 132     // keys rows
#define H1PITCH 68     // h1 rows
#define H2PITCH 33     // h2 rows (scalar access only)
// transposed weights, [out][in]:
#define W1TP 132       // W1T rows (64 rows x 128 e)
#define W2TP 68        // W2T rows (32 rows x 64 e)

// shared-memory float offsets
#define OFF_KEYS 0
#define OFF_H1   (S_ * KPITCH)                  // 26400 (13600) ; phase-1 partials alias here
#define OFF_W1T  (OFF_H1 + S_ * H1PITCH)        // 40000 (8448)
#define OFF_W2T  (OFF_W1T + H_ * W1TP)          // 48448 (2176)
#define OFF_H2   (OFF_W2T + G_ * W2TP)          // 50624 (6600)
#define OFF_Q    (OFF_H2)                       // alias: used phases 0-1, H2 written phase 3
#define OFF_RED  (OFF_H2 + 128)                 // alias: used phase 5, H2 dead after phase 4
#define OFF_PART (OFF_H2 + 160)                 // alias: used phase 6 (512 floats)
#define OFF_W3   (OFF_H2 + S_ * H2PITCH)        // 57224 (32)
#define OFF_QP   (OFF_W3 + G_)                  // 57256 (64)
#define OFF_SC   (OFF_QP + H_)                  // 57320 (200)
#define SMEM_FLOATS (OFF_SC + S_)               // 57520
#define SMEM_BYTES (SMEM_FLOATS * 4)            // 230080 (< 232448)

// ---- packed f32x2 helpers ----
__device__ __forceinline__ void fma2(unsigned long long& d,
                                     unsigned long long a,
                                     unsigned long long b) {
    asm("fma.rn.f32x2 %0, %1, %2, %0;" : "+l"(d) : "l"(a), "l"(b));
}
__device__ __forceinline__ float2 unpack2(unsigned long long v) {
    float2 f;
    asm("mov.b64 {%0, %1}, %2;" : "=f"(f.x), "=f"(f.y) : "l"(v));
    return f;
}

__global__ __launch_bounds__(NT, 1)
void attn_mlp_kernel(const float* __restrict__ query,
                     const float* __restrict__ keys,
                     const int*   __restrict__ mask,
                     const float* __restrict__ W1,
                     const float* __restrict__ b1,
                     const float* __restrict__ W2,
                     const float* __restrict__ b2,
                     const float* __restrict__ W3,
                     const float* __restrict__ b3,
                     float* __restrict__ out_att,
                     float* __restrict__ out_w)
{
    extern __shared__ float sm[];
    const int b = blockIdx.x;
    const int t = threadIdx.x;

    // ---------------- Phase 0: stage inputs into shared memory ----------------
    // keys[b] : 200x128 f32, pitch 132
    {
        const float4* kg = reinterpret_cast<const float4*>(keys + (size_t)b * S_ * E_);
        for (int fi = t; fi < (S_ * E_) / 4; fi += NT) {
            float4 v = kg[fi];
            int s = fi >> 5;
            int c = (fi & 31) * 4;
            *reinterpret_cast<float4*>(&sm[OFF_KEYS + s * KPITCH + c]) = v;
        }
    }
    // W1 bottom half (keys part) rows 128..255, TRANSPOSED to [j][e], pitch 132
    {
        const float4* wg = reinterpret_cast<const float4*>(W1 + E_ * H_);
        for (int fi = t; fi < (E_ * H_) / 4; fi += NT) {
            float4 v = wg[fi];              // W1[128+e][4j4..4j4+3]
            int e  = fi >> 4;
            int j4 = (fi & 15) * 4;
            sm[OFF_W1T + (j4 + 0) * W1TP + e] = v.x;
            sm[OFF_W1T + (j4 + 1) * W1TP + e] = v.y;
            sm[OFF_W1T + (j4 + 2) * W1TP + e] = v.z;
            sm[OFF_W1T + (j4 + 3) * W1TP + e] = v.w;
        }
    }
    // W2 : [e=64][g=32], TRANSPOSED to [g][e], pitch 68
    {
        const float4* wg = reinterpret_cast<const float4*>(W2);
        for (int fi = t; fi < (H_ * G_) / 4; fi += NT) {
            float4 v = wg[fi];              // W2[e][4g4..4g4+3]
            int e  = fi >> 3;
            int g4 = (fi & 7) * 4;
            sm[OFF_W2T + (g4 + 0) * W2TP + e] = v.x;
            sm[OFF_W2T + (g4 + 1) * W2TP + e] = v.y;
            sm[OFF_W2T + (g4 + 2) * W2TP + e] = v.z;
            sm[OFF_W2T + (g4 + 3) * W2TP + e] = v.w;
        }
    }
    if (t < G_) sm[OFF_W3 + t] = W3[t];
    if (t < E_) sm[OFF_Q + t] = query[(size_t)b * E_ + t];
    __syncthreads();

    // -------- Phase 1: query part of layer 1, parallel over all threads --------
    // qp[j] = b1[j] + sum_e q[e]*W1[e][j]; 8 partials per j (part = t>>6)
    {
        const int tj = t & 63;
        const int part = t >> 6;
        float p = 0.f;
        #pragma unroll
        for (int k = 0; k < 16; k++) {
            int e = part * 16 + k;
            p += sm[OFF_Q + e] * W1[e * H_ + tj];   // coalesced LDG per e
        }
        sm[OFF_H1 + part * 64 + tj] = p;            // H1 region free here
    }
    __syncthreads();
    if (t < H_) {
        float acc = b1[t];
        #pragma unroll
        for (int p = 0; p < 8; p++) acc += sm[OFF_H1 + p * 64 + t];
        sm[OFF_QP + t] = acc;
    }
    __syncthreads();

    // ------- Phase 2: layer 1  h1[s][j] = relu(qp[j] + K[s,:]·W1b[:,j]) -------
    // Even/odd-e packed accumulation: acc.lo = even e, acc.hi = odd e. No packs.
    {
        const int jt = t & 15;     // j set: jt, jt+16, jt+32, jt+48
        const int st = t >> 4;     // s rows: st + 32*i, i = 0..6
        unsigned long long acc[7][4];
        #pragma unroll
        for (int i = 0; i < 7; i++)
            #pragma unroll
            for (int c = 0; c < 4; c++) acc[i][c] = 0ull;

        const ulonglong2* kvec = reinterpret_cast<const ulonglong2*>(&sm[OFF_KEYS]);
        const ulonglong2* w1t  = reinterpret_cast<const ulonglong2*>(&sm[OFF_W1T]);
        int kb[7];
        #pragma unroll
        for (int i = 0; i < 7; i++) kb[i] = (st + 32 * i) * (KPITCH / 4);

        #pragma unroll 1
        for (int eb = 0; eb < E_ / 4; eb++) {
            ulonglong2 w0 = w1t[(jt +  0) * (W1TP / 4) + eb];
            ulonglong2 w1 = w1t[(jt + 16) * (W1TP / 4) + eb];
            ulonglong2 w2 = w1t[(jt + 32) * (W1TP / 4) + eb];
            ulonglong2 w3 = w1t[(jt + 48) * (W1TP / 4) + eb];
            #pragma unroll
            for (int i = 0; i < 7; i++) {
                ulonglong2 kv = kvec[kb[i] + eb];
                fma2(acc[i][0], kv.x, w0.x); fma2(acc[i][0], kv.y, w0.y);
                fma2(acc[i][1], kv.x, w1.x); fma2(acc[i][1], kv.y, w1.y);
                fma2(acc[i][2], kv.x, w2.x); fma2(acc[i][2], kv.y, w2.y);
                fma2(acc[i][3], kv.x, w3.x); fma2(acc[i][3], kv.y, w3.y);
            }
        }
        float qp0 = sm[OFF_QP + jt +  0];
        float qp1 = sm[OFF_QP + jt + 16];
        float qp2 = sm[OFF_QP + jt + 32];
        float qp3 = sm[OFF_QP + jt + 48];
        #pragma unroll
        for (int i = 0; i < 7; i++) {
            int s = st + 32 * i;
            if (s < S_) {
                float2 a0 = unpack2(acc[i][0]);
                float2 a1 = unpack2(acc[i][1]);
                float2 a2 = unpack2(acc[i][2]);
                float2 a3 = unpack2(acc[i][3]);
                float* d = &sm[OFF_H1 + s * H1PITCH];
                d[jt +  0] = fmaxf(a0.x + a0.y + qp0, 0.f);
                d[jt + 16] = fmaxf(a1.x + a1.y + qp1, 0.f);
                d[jt + 32] = fmaxf(a2.x + a2.y + qp2, 0.f);
                d[jt + 48] = fmaxf(a3.x + a3.y + qp3, 0.f);
            }
        }
    }
    __syncthreads();

    // ------- Phase 3: layer 2  h2[s][g] = relu(h1[s,:]·W2[:,g] + b2[g]) -------
    {
        const int gt = t & 7;      // g set: gt, gt+8, gt+16, gt+24
        const int st = t >> 3;     // s rows: st + 64*i, i = 0..3
        unsigned long long acc[4][4];
        #pragma unroll
        for (int i = 0; i < 4; i++)
            #pragma unroll
            for (int c = 0; c < 4; c++) acc[i][c] = 0ull;

        const ulonglong2* h1v = reinterpret_cast<const ulonglong2*>(&sm[OFF_H1]);
        const ulonglong2* w2t = reinterpret_cast<const ulonglong2*>(&sm[OFF_W2T]);
        int hb[4];
        #pragma unroll
        for (int i = 0; i < 4; i++) hb[i] = (st + 64 * i) * (H1PITCH / 4);

        #pragma unroll 1
        for (int eb = 0; eb < H_ / 4; eb++) {
            ulonglong2 w0 = w2t[(gt +  0) * (W2TP / 4) + eb];
            ulonglong2 w1 = w2t[(gt +  8) * (W2TP / 4) + eb];
            ulonglong2 w2 = w2t[(gt + 16) * (W2TP / 4) + eb];
            ulonglong2 w3 = w2t[(gt + 24) * (W2TP / 4) + eb];
            #pragma unroll
            for (int i = 0; i < 4; i++) {
                // rows s >= 200 read in-bounds junk (finite), guarded at store
                ulonglong2 hv = h1v[hb[i] + eb];
                fma2(acc[i][0], hv.x, w0.x); fma2(acc[i][0], hv.y, w0.y);
                fma2(acc[i][1], hv.x, w1.x); fma2(acc[i][1], hv.y, w1.y);
                fma2(acc[i][2], hv.x, w2.x); fma2(acc[i][2], hv.y, w2.y);
                fma2(acc[i][3], hv.x, w3.x); fma2(acc[i][3], hv.y, w3.y);
            }
        }
        float bb0 = b2[gt +  0];
        float bb1 = b2[gt +  8];
        float bb2 = b2[gt + 16];
        float bb3 = b2[gt + 24];
        #pragma unroll
        for (int i = 0; i < 4; i++) {
            int s = st + 64 * i;
            if (s < S_) {
                float2 a0 = unpack2(acc[i][0]);
                float2 a1 = unpack2(acc[i][1]);
                float2 a2 = unpack2(acc[i][2]);
                float2 a3 = unpack2(acc[i][3]);
                float* d = &sm[OFF_H2 + s * H2PITCH];
                d[gt +  0] = fmaxf(a0.x + a0.y + bb0, 0.f);
                d[gt +  8] = fmaxf(a1.x + a1.y + bb1, 0.f);
                d[gt + 16] = fmaxf(a2.x + a2.y + bb2, 0.f);
                d[gt + 24] = fmaxf(a3.x + a3.y + bb3, 0.f);
            }
        }
    }
    __syncthreads();

    // ---------------- Phase 4: layer 3 + mask -> scores ----------------
    if (t < S_) {
        float a0 = b3[0], a1 = 0.f, a2 = 0.f, a3 = 0.f;
        #pragma unroll
        for (int g = 0; g < G_; g += 4) {
            a0 += sm[OFF_H2 + t * H2PITCH + g + 0] * sm[OFF_W3 + g + 0];
            a1 += sm[OFF_H2 + t * H2PITCH + g + 1] * sm[OFF_W3 + g + 1];
            a2 += sm[OFF_H2 + t * H2PITCH + g + 2] * sm[OFF_W3 + g + 2];
            a3 += sm[OFF_H2 + t * H2PITCH + g + 3] * sm[OFF_W3 + g + 3];
        }
        float acc = (a0 + a1) + (a2 + a3);
        if (mask[(size_t)b * S_ + t] == 0) acc = -1e9f;
        sm[OFF_SC + t] = acc;
    }
    __syncthreads();

    // ---------------- Phase 5: softmax over s ----------------
    const int lane = t & 31;
    const int warp = t >> 5;
    {
        float v = (t < S_) ? sm[OFF_SC + t] : -3.4e38f;
        #pragma unroll
        for (int o = 16; o > 0; o >>= 1)
            v = fmaxf(v, __shfl_xor_sync(0xFFFFFFFFu, v, o));
        if (lane == 0) sm[OFF_RED + warp] = v;
    }
    __syncthreads();
    float mx = sm[OFF_RED + 0];
    #pragma unroll
    for (int w = 1; w < NT / 32; w++) mx = fmaxf(mx, sm[OFF_RED + w]);

    float ev = (t < S_) ? expf(sm[OFF_SC + t] - mx) : 0.f;
    {
        float v = ev;
        #pragma unroll
        for (int o = 16; o > 0; o >>= 1)
            v += __shfl_xor_sync(0xFFFFFFFFu, v, o);
        if (lane == 0) sm[OFF_RED + 16 + warp] = v;
    }
    __syncthreads();
    float tot = sm[OFF_RED + 16];
    #pragma unroll
    for (int w = 1; w < NT / 32; w++) tot += sm[OFF_RED + 16 + w];
    float inv = 1.0f / tot;
    if (t < S_) {
        float w = ev * inv;
        sm[OFF_SC + t] = w;
        out_w[(size_t)b * S_ + t] = w;
    }
    __syncthreads();

    // ---------------- Phase 6: attended = sum_s w[s] * keys[s,:] ----------------
    {
        const int e = t & 127;
        const int q = t >> 7;          // quarter: s in [q*50, q*50+50)
        float a0 = 0.f, a1 = 0.f;
        const int s0 = q * 50;
        #pragma unroll 5
        for (int s = s0; s < s0 + 50; s += 2) {
            a0 += sm[OFF_SC + s + 0] * sm[OFF_KEYS + (s + 0) * KPITCH + e];
            a1 += sm[OFF_SC + s + 1] * sm[OFF_KEYS + (s + 1) * KPITCH + e];
        }
        sm[OFF_PART + q * E_ + e] = a0 + a1;
    }
    __syncthreads();
    if (t < E_)
        out_att[(size_t)b * E_ + t] = (sm[OFF_PART + t] + sm[OFF_PART + E_ + t])
                                    + (sm[OFF_PART + 2 * E_ + t] + sm[OFF_PART + 3 * E_ + t]);
}

extern "C" void kernel_launch(void* const* d_in, const int* in_sizes, int n_in,
                              void* d_out, int out_size) {
    const float* query = (const float*)d_in[0];
    const float* keys  = (const float*)d_in[1];
    const int*   mask  = (const int*)  d_in[2];
    const float* W1    = (const float*)d_in[3];
    const float* b1    = (const float*)d_in[4];
    const float* W2    = (const float*)d_in[5];
    const float* b2    = (const float*)d_in[6];
    const float* W3    = (const float*)d_in[7];
    const float* b3    = (const float*)d_in[8];

    float* out = (float*)d_out;
    float* out_att = out;                       // [B, E] first (tuple order)
    float* out_w   = out + (size_t)B_ * E_;     // [B, S] second

    cudaFuncSetAttribute(attn_mlp_kernel,
                         cudaFuncAttributeMaxDynamicSharedMemorySize, SMEM_BYTES);

    attn_mlp_kernel<<<B_, NT, SMEM_BYTES>>>(query, keys, mask,
                                            W1, b1, W2, b2, W3, b3,
                                            out_att, out_w);
}